// round 4
// baseline (speedup 1.0000x reference)
#include <cuda_runtime.h>
#include <cuda_fp16.h>
#include <cstdint>

#define NR 8192
#define MC 8192
#define DD 64

// ---------------- device-global staging (no allocation allowed) ----------------
__device__ __align__(16) __half g_ah[NR * DD];
__device__ __align__(16) __half g_al[NR * DD];
__device__ __align__(16) __half g_bh[MC * DD];
__device__ __align__(16) __half g_bl[MC * DD];
// per-row stats: x = |p|^2, y = 2/(1-|a|^2) for a-rows, 1/(1-|b|^2) for b-rows
__device__ float2 g_apa[NR];
__device__ float2 g_bq[MC];

// ---------------- helpers ----------------
__device__ __forceinline__ float fast_sqrt(float x) {
    float r; asm("sqrt.approx.f32 %0, %1;" : "=f"(r) : "f"(x)); return r;
}
__device__ __forceinline__ uint32_t smem_u32(const void* p) {
    uint32_t a;
    asm("{ .reg .u64 t; cvta.to.shared.u64 t, %1; cvt.u32.u64 %0, t; }" : "=r"(a) : "l"(p));
    return a;
}
#define CP_ASYNC16(dst, src) \
    asm volatile("cp.async.cg.shared.global [%0], [%1], 16;" :: "r"(dst), "l"(src) : "memory")
#define CP_COMMIT() asm volatile("cp.async.commit_group;" ::: "memory")
#define CP_WAIT0()  asm volatile("cp.async.wait_group 0;" ::: "memory")

#define LDSM4(R, a) \
    asm volatile("ldmatrix.sync.aligned.m8n8.x4.shared.b16 {%0,%1,%2,%3}, [%4];" \
        : "=r"((R)[0]), "=r"((R)[1]), "=r"((R)[2]), "=r"((R)[3]) : "r"(a))

#define MMA16816(d, a, b0, b1) \
    asm volatile("mma.sync.aligned.m16n8k16.row.col.f32.f16.f16.f32 " \
        "{%0,%1,%2,%3}, {%4,%5,%6,%7}, {%8,%9}, {%0,%1,%2,%3};" \
        : "+f"((d)[0]), "+f"((d)[1]), "+f"((d)[2]), "+f"((d)[3]) \
        : "r"((a)[0]), "r"((a)[1]), "r"((a)[2]), "r"((a)[3]), "r"(b0), "r"(b1))

// ---------------- prep: norms + reciprocal terms + fp16 hi/lo split ----------------
__global__ void poincare_prep_kernel(const float* __restrict__ a,
                                     const float* __restrict__ b) {
    int warp = (blockIdx.x * blockDim.x + threadIdx.x) >> 5;
    int lane = threadIdx.x & 31;
    const float* row;
    __half *dh, *dl;
    bool isA = warp < NR;
    int r = isA ? warp : warp - NR;
    if (isA) { row = a + (size_t)r * DD; dh = g_ah + (size_t)r * DD; dl = g_al + (size_t)r * DD; }
    else     { row = b + (size_t)r * DD; dh = g_bh + (size_t)r * DD; dl = g_bl + (size_t)r * DD; }

    float v0 = row[lane], v1 = row[lane + 32];
    __half h0 = __float2half_rn(v0);
    __half l0 = __float2half_rn(v0 - __half2float(h0));
    __half h1 = __float2half_rn(v1);
    __half l1 = __float2half_rn(v1 - __half2float(h1));
    dh[lane] = h0;  dh[lane + 32] = h1;
    dl[lane] = l0;  dl[lane + 32] = l1;

    float s = fmaf(v0, v0, v1 * v1);
    #pragma unroll
    for (int o = 16; o > 0; o >>= 1) s += __shfl_xor_sync(0xffffffffu, s, o);
    if (lane == 0) {
        if (isA) g_apa[r] = make_float2(s, 2.0f / (1.0f - s));
        else     g_bq[r]  = make_float2(s, 1.0f / (1.0f - s));
    }
}

// ---------------- main: fp16-split HMMA GEMM + fused Poincare epilogue ----------------
// CTA tile 128(M: a-rows) x 128(N: b-rows), K = 64 in one shot.
// 8 warps: warp grid 2(M) x 4(N); warp tile 64x32.
#define PITCH 144   // smem row pitch bytes (128 data + 16 pad) -> ldmatrix conflict-free
#define TILE_BYTES (128 * PITCH)

__global__ void __launch_bounds__(256)
poincare_hmma_kernel(float* __restrict__ out) {
    extern __shared__ char smem[];
    char* sAh = smem;
    char* sAl = smem + TILE_BYTES;
    char* sBh = smem + 2 * TILE_BYTES;
    char* sBl = smem + 3 * TILE_BYTES;

    const int tid = threadIdx.x;
    const int lane = tid & 31;
    const int wid = tid >> 5;
    const int wm = wid >> 2;       // 0..1
    const int wn = wid & 3;        // 0..3

    const int row0 = blockIdx.y * 128;   // a-rows
    const int col0 = blockIdx.x * 128;   // b-rows

    // ---- stage all 4 tiles via cp.async (each 128 rows x 128B) ----
    {
        const uint32_t sb = smem_u32(smem);
        #pragma unroll
        for (int t = 0; t < 4; t++) {
            int chunk = tid + 256 * t;      // 0..1023
            int r = chunk >> 3;
            int kc = chunk & 7;
            uint32_t doff = (uint32_t)(r * PITCH + kc * 16);
            CP_ASYNC16(sb + 0 * TILE_BYTES + doff, g_ah + (size_t)(row0 + r) * DD + kc * 8);
            CP_ASYNC16(sb + 1 * TILE_BYTES + doff, g_al + (size_t)(row0 + r) * DD + kc * 8);
            CP_ASYNC16(sb + 2 * TILE_BYTES + doff, g_bh + (size_t)(col0 + r) * DD + kc * 8);
            CP_ASYNC16(sb + 3 * TILE_BYTES + doff, g_bl + (size_t)(col0 + r) * DD + kc * 8);
        }
        CP_COMMIT();
        CP_WAIT0();
    }
    __syncthreads();

    // ---- accumulators: 4 M-frags x 4 N-frags x 4 floats ----
    float acc[4][4][4];
    #pragma unroll
    for (int i = 0; i < 4; i++)
        #pragma unroll
        for (int j = 0; j < 4; j++)
            #pragma unroll
            for (int q = 0; q < 4; q++) acc[i][j][q] = 0.0f;

    // ldmatrix lane addressing
    const uint32_t a_row  = (uint32_t)(wm * 64 + (lane & 15));
    const uint32_t a_koff = (uint32_t)((lane >> 4) * 16);
    const uint32_t b_row  = (uint32_t)(wn * 32 + ((lane & 16) >> 1) + (lane & 7));
    const uint32_t b_koff = (uint32_t)(((lane >> 3) & 1) * 16);

    const uint32_t uAh = smem_u32(sAh), uAl = smem_u32(sAl);
    const uint32_t uBh = smem_u32(sBh), uBl = smem_u32(sBl);

    #pragma unroll
    for (int ks = 0; ks < 4; ks++) {
        const uint32_t kb = (uint32_t)(ks * 32);
        uint32_t Ah[4][4], Al[4][4];
        #pragma unroll
        for (int mf = 0; mf < 4; mf++) {
            uint32_t off = (a_row + mf * 16) * PITCH + kb + a_koff;
            LDSM4(Ah[mf], uAh + off);
            LDSM4(Al[mf], uAl + off);
        }
        uint32_t Bh[2][4], Bl[2][4];
        #pragma unroll
        for (int nh = 0; nh < 2; nh++) {
            uint32_t off = (b_row + nh * 16) * PITCH + kb + b_koff;
            LDSM4(Bh[nh], uBh + off);
            LDSM4(Bl[nh], uBl + off);
        }

        // ---- PASS-MAJOR ordering: same-accumulator reuse distance = 16 MMAs,
        //      so the HMMA RAW latency is fully pipelined. ----
        #pragma unroll
        for (int nf = 0; nf < 4; nf++) {          // hi*hi
            uint32_t b0 = Bh[nf >> 1][(nf & 1) * 2], b1 = Bh[nf >> 1][(nf & 1) * 2 + 1];
            #pragma unroll
            for (int mf = 0; mf < 4; mf++)
                MMA16816(acc[mf][nf], Ah[mf], b0, b1);
        }
        #pragma unroll
        for (int nf = 0; nf < 4; nf++) {          // hi*lo
            uint32_t b0 = Bl[nf >> 1][(nf & 1) * 2], b1 = Bl[nf >> 1][(nf & 1) * 2 + 1];
            #pragma unroll
            for (int mf = 0; mf < 4; mf++)
                MMA16816(acc[mf][nf], Ah[mf], b0, b1);
        }
        #pragma unroll
        for (int nf = 0; nf < 4; nf++) {          // lo*hi
            uint32_t b0 = Bh[nf >> 1][(nf & 1) * 2], b1 = Bh[nf >> 1][(nf & 1) * 2 + 1];
            #pragma unroll
            for (int mf = 0; mf < 4; mf++)
                MMA16816(acc[mf][nf], Al[mf], b0, b1);
        }
    }

    // ---- fused Poincare epilogue ----
    // c frag: c0,c1 = (row = lane/4, col = 2*(lane%4)+{0,1}); c2,c3 = row+8
    const int er = row0 + wm * 64 + (lane >> 2);
    const int ec = col0 + wn * 32 + 2 * (lane & 3);

    float2 rs[4][2];   // row stats per mf: {row, row+8}
    float2 cs[4][2];   // col stats per nf: {col, col+1}
    #pragma unroll
    for (int mf = 0; mf < 4; mf++) {
        rs[mf][0] = g_apa[er + mf * 16];
        rs[mf][1] = g_apa[er + mf * 16 + 8];
    }
    #pragma unroll
    for (int nf = 0; nf < 4; nf++) {
        cs[nf][0] = g_bq[ec + nf * 8];
        cs[nf][1] = g_bq[ec + nf * 8 + 1];
    }

    #pragma unroll
    for (int mf = 0; mf < 4; mf++) {
        #pragma unroll
        for (int nf = 0; nf < 4; nf++) {
            float res[4];
            #pragma unroll
            for (int q = 0; q < 4; q++) {
                float2 ra = rs[mf][q >> 1];
                float2 cb = cs[nf][q & 1];
                float sq = fmaf(-2.0f, acc[mf][nf][q], ra.x + cb.x);
                float d  = fast_sqrt(fmaxf(sq, 0.0f));
                float y  = d * (ra.y * cb.y);
                float tt = fmaf(y, y, y + y);
                res[q] = __logf(1.0f + y + fast_sqrt(tt));
            }
            size_t r0 = (size_t)(er + mf * 16) * MC + (ec + nf * 8);
            *reinterpret_cast<float2*>(out + r0)            = make_float2(res[0], res[1]);
            *reinterpret_cast<float2*>(out + r0 + 8 * MC)   = make_float2(res[2], res[3]);
        }
    }
}

extern "C" void kernel_launch(void* const* d_in, const int* in_sizes, int n_in,
                              void* d_out, int out_size) {
    const float* a = (const float*)d_in[0];
    const float* b = (const float*)d_in[1];
    float* out = (float*)d_out;

    cudaFuncSetAttribute(poincare_hmma_kernel,
                         cudaFuncAttributeMaxDynamicSharedMemorySize, 4 * TILE_BYTES);

    poincare_prep_kernel<<<(NR + MC) / 8, 256>>>(a, b);
    dim3 grid(MC / 128, NR / 128);
    poincare_hmma_kernel<<<grid, 256, 4 * TILE_BYTES>>>(out);
}

// round 5
// speedup vs baseline: 1.0209x; 1.0209x over previous
#include <cuda_runtime.h>
#include <cuda_fp16.h>
#include <cstdint>

#define NR 8192
#define MC 8192
#define DD 64

// ---------------- device-global staging (no allocation allowed) ----------------
__device__ __align__(16) __half g_ah[NR * DD];
__device__ __align__(16) __half g_al[NR * DD];
__device__ __align__(16) __half g_bh[MC * DD];
__device__ __align__(16) __half g_bl[MC * DD];
// per-row stats: x = |p|^2, y = 2/(1-|a|^2) for a-rows, 1/(1-|b|^2) for b-rows
__device__ float2 g_apa[NR];
__device__ float2 g_bq[MC];

// ---------------- helpers ----------------
__device__ __forceinline__ float fast_sqrt(float x) {
    float r; asm("sqrt.approx.f32 %0, %1;" : "=f"(r) : "f"(x)); return r;
}
__device__ __forceinline__ uint32_t smem_u32(const void* p) {
    uint32_t a;
    asm("{ .reg .u64 t; cvta.to.shared.u64 t, %1; cvt.u32.u64 %0, t; }" : "=r"(a) : "l"(p));
    return a;
}
#define CP_ASYNC16(dst, src) \
    asm volatile("cp.async.cg.shared.global [%0], [%1], 16;" :: "r"(dst), "l"(src) : "memory")
#define CP_COMMIT() asm volatile("cp.async.commit_group;" ::: "memory")
#define CP_WAIT0()  asm volatile("cp.async.wait_group 0;" ::: "memory")

#define LDSM4(R, a) \
    asm volatile("ldmatrix.sync.aligned.m8n8.x4.shared.b16 {%0,%1,%2,%3}, [%4];" \
        : "=r"((R)[0]), "=r"((R)[1]), "=r"((R)[2]), "=r"((R)[3]) : "r"(a))

#define MMA16816(d, a, b0, b1) \
    asm volatile("mma.sync.aligned.m16n8k16.row.col.f32.f16.f16.f32 " \
        "{%0,%1,%2,%3}, {%4,%5,%6,%7}, {%8,%9}, {%0,%1,%2,%3};" \
        : "+f"((d)[0]), "+f"((d)[1]), "+f"((d)[2]), "+f"((d)[3]) \
        : "r"((a)[0]), "r"((a)[1]), "r"((a)[2]), "r"((a)[3]), "r"(b0), "r"(b1))

// ---------------- prep: norms + reciprocal terms + fp16 hi/lo split ----------------
__global__ void poincare_prep_kernel(const float* __restrict__ a,
                                     const float* __restrict__ b) {
    int warp = (blockIdx.x * blockDim.x + threadIdx.x) >> 5;
    int lane = threadIdx.x & 31;
    const float* row;
    __half *dh, *dl;
    bool isA = warp < NR;
    int r = isA ? warp : warp - NR;
    if (isA) { row = a + (size_t)r * DD; dh = g_ah + (size_t)r * DD; dl = g_al + (size_t)r * DD; }
    else     { row = b + (size_t)r * DD; dh = g_bh + (size_t)r * DD; dl = g_bl + (size_t)r * DD; }

    float v0 = row[lane], v1 = row[lane + 32];
    __half h0 = __float2half_rn(v0);
    __half l0 = __float2half_rn(v0 - __half2float(h0));
    __half h1 = __float2half_rn(v1);
    __half l1 = __float2half_rn(v1 - __half2float(h1));
    dh[lane] = h0;  dh[lane + 32] = h1;
    dl[lane] = l0;  dl[lane + 32] = l1;

    float s = fmaf(v0, v0, v1 * v1);
    #pragma unroll
    for (int o = 16; o > 0; o >>= 1) s += __shfl_xor_sync(0xffffffffu, s, o);
    if (lane == 0) {
        if (isA) g_apa[r] = make_float2(s, 2.0f / (1.0f - s));
        else     g_bq[r]  = make_float2(s, 1.0f / (1.0f - s));
    }
}

// ---------------- main: fp16-split HMMA GEMM + fused Poincare epilogue ----------------
// CTA tile 64(M: a-rows) x 128(N: b-rows), K = 64 in one shot.
// 8 warps: warp grid 2(M) x 4(N); warp tile 32x32. 3 CTAs/SM for phase overlap.
#define PITCH 144   // smem row pitch bytes (128 data + 16 pad) -> ldmatrix conflict-free
#define A_TILE_BYTES (64 * PITCH)
#define B_TILE_BYTES (128 * PITCH)
#define SMEM_TOTAL (2 * A_TILE_BYTES + 2 * B_TILE_BYTES)   // 55296

__global__ void __launch_bounds__(256, 3)
poincare_hmma_kernel(float* __restrict__ out) {
    extern __shared__ char smem[];
    char* sAh = smem;
    char* sAl = smem + A_TILE_BYTES;
    char* sBh = smem + 2 * A_TILE_BYTES;
    char* sBl = smem + 2 * A_TILE_BYTES + B_TILE_BYTES;

    const int tid = threadIdx.x;
    const int lane = tid & 31;
    const int wid = tid >> 5;
    const int wm = wid >> 2;       // 0..1  (M strip of 32)
    const int wn = wid & 3;        // 0..3  (N strip of 32)

    const int row0 = blockIdx.y * 64;    // a-rows
    const int col0 = blockIdx.x * 128;   // b-rows

    // ---- stage tiles via cp.async ----
    {
        const uint32_t sb = smem_u32(smem);
        // A tiles: 64 rows x 8 chunks = 512 cp.async each (2 iters of 256)
        #pragma unroll
        for (int t = 0; t < 2; t++) {
            int chunk = tid + 256 * t;          // 0..511
            int r = chunk >> 3;
            int kc = chunk & 7;
            uint32_t doff = (uint32_t)(r * PITCH + kc * 16);
            CP_ASYNC16(sb + doff, g_ah + (size_t)(row0 + r) * DD + kc * 8);
            CP_ASYNC16(sb + A_TILE_BYTES + doff, g_al + (size_t)(row0 + r) * DD + kc * 8);
        }
        // B tiles: 128 rows x 8 chunks = 1024 each (4 iters)
        #pragma unroll
        for (int t = 0; t < 4; t++) {
            int chunk = tid + 256 * t;          // 0..1023
            int r = chunk >> 3;
            int kc = chunk & 7;
            uint32_t doff = (uint32_t)(r * PITCH + kc * 16);
            CP_ASYNC16(sb + 2 * A_TILE_BYTES + doff,
                       g_bh + (size_t)(col0 + r) * DD + kc * 8);
            CP_ASYNC16(sb + 2 * A_TILE_BYTES + B_TILE_BYTES + doff,
                       g_bl + (size_t)(col0 + r) * DD + kc * 8);
        }
        CP_COMMIT();
        CP_WAIT0();
    }
    __syncthreads();

    // ---- hoist epilogue stats loads: latency hides under MMA issue ----
    const int er = row0 + wm * 32 + (lane >> 2);
    const int ec = col0 + wn * 32 + 2 * (lane & 3);
    float2 rs[2][2];   // row stats per mf: {row, row+8}
    float2 cs[4][2];   // col stats per nf: {col, col+1}
    #pragma unroll
    for (int mf = 0; mf < 2; mf++) {
        rs[mf][0] = __ldg(&g_apa[er + mf * 16]);
        rs[mf][1] = __ldg(&g_apa[er + mf * 16 + 8]);
    }
    #pragma unroll
    for (int nf = 0; nf < 4; nf++) {
        cs[nf][0] = __ldg(&g_bq[ec + nf * 8]);
        cs[nf][1] = __ldg(&g_bq[ec + nf * 8 + 1]);
    }

    // ---- accumulators: 2 M-frags x 4 N-frags x 4 floats ----
    float acc[2][4][4];
    #pragma unroll
    for (int i = 0; i < 2; i++)
        #pragma unroll
        for (int j = 0; j < 4; j++)
            #pragma unroll
            for (int q = 0; q < 4; q++) acc[i][j][q] = 0.0f;

    // ldmatrix lane addressing
    const uint32_t a_row  = (uint32_t)(wm * 32 + (lane & 15));
    const uint32_t a_koff = (uint32_t)((lane >> 4) * 16);
    const uint32_t b_row  = (uint32_t)(wn * 32 + ((lane & 16) >> 1) + (lane & 7));
    const uint32_t b_koff = (uint32_t)(((lane >> 3) & 1) * 16);

    const uint32_t uAh = smem_u32(sAh), uAl = smem_u32(sAl);
    const uint32_t uBh = smem_u32(sBh), uBl = smem_u32(sBl);

    #pragma unroll
    for (int ks = 0; ks < 4; ks++) {
        const uint32_t kb = (uint32_t)(ks * 32);
        uint32_t Ah[2][4], Al[2][4];
        #pragma unroll
        for (int mf = 0; mf < 2; mf++) {
            uint32_t off = (a_row + mf * 16) * PITCH + kb + a_koff;
            LDSM4(Ah[mf], uAh + off);
            LDSM4(Al[mf], uAl + off);
        }
        uint32_t Bh[2][4], Bl[2][4];
        #pragma unroll
        for (int nh = 0; nh < 2; nh++) {
            uint32_t off = (b_row + nh * 16) * PITCH + kb + b_koff;
            LDSM4(Bh[nh], uBh + off);
            LDSM4(Bl[nh], uBl + off);
        }
        #pragma unroll
        for (int nf = 0; nf < 4; nf++) {
            uint32_t bh0 = Bh[nf >> 1][(nf & 1) * 2], bh1 = Bh[nf >> 1][(nf & 1) * 2 + 1];
            uint32_t bl0 = Bl[nf >> 1][(nf & 1) * 2], bl1 = Bl[nf >> 1][(nf & 1) * 2 + 1];
            #pragma unroll
            for (int mf = 0; mf < 2; mf++) {
                MMA16816(acc[mf][nf], Ah[mf], bh0, bh1);   // hi*hi
                MMA16816(acc[mf][nf], Ah[mf], bl0, bl1);   // hi*lo
                MMA16816(acc[mf][nf], Al[mf], bh0, bh1);   // lo*hi
            }
        }
    }

    // ---- fused Poincare epilogue ----
    #pragma unroll
    for (int mf = 0; mf < 2; mf++) {
        #pragma unroll
        for (int nf = 0; nf < 4; nf++) {
            float res[4];
            #pragma unroll
            for (int q = 0; q < 4; q++) {
                float2 ra = rs[mf][q >> 1];
                float2 cb = cs[nf][q & 1];
                float c  = ra.y * cb.y;               // combined reciprocal factor
                float sq = fmaf(-2.0f, acc[mf][nf][q], ra.x + cb.x);
                sq = fmaxf(sq, 0.0f);
                float y2 = (sq * c) * c;              // y^2 without waiting for sqrt
                float d  = fast_sqrt(sq);
                float y  = d * c;
                float tt = fmaf(2.0f, y, y2);         // y^2 + 2y
                res[q] = __logf(1.0f + y + fast_sqrt(tt));
            }
            size_t r0 = (size_t)(er + mf * 16) * MC + (ec + nf * 8);
            *reinterpret_cast<float2*>(out + r0)          = make_float2(res[0], res[1]);
            *reinterpret_cast<float2*>(out + r0 + 8 * MC) = make_float2(res[2], res[3]);
        }
    }
}

extern "C" void kernel_launch(void* const* d_in, const int* in_sizes, int n_in,
                              void* d_out, int out_size) {
    const float* a = (const float*)d_in[0];
    const float* b = (const float*)d_in[1];
    float* out = (float*)d_out;

    cudaFuncSetAttribute(poincare_hmma_kernel,
                         cudaFuncAttributeMaxDynamicSharedMemorySize, SMEM_TOTAL);

    poincare_prep_kernel<<<(NR + MC) / 8, 256>>>(a, b);
    dim3 grid(MC / 128, NR / 64);
    poincare_hmma_kernel<<<grid, 256, SMEM_TOTAL>>>(out);
}